// round 9
// baseline (speedup 1.0000x reference)
#include <cuda_runtime.h>

#define BB 8
#define NSEQ 256
#define DD 300
#define KHALF 150
#define MROWS (BB*NSEQ)          // 2048
#define FEATW 512                // left | right | hs | he

typedef unsigned long long ull;

// K-half partials, combined features, pre-duplicated B
__device__ float g_part0[MROWS * FEATW];
__device__ float g_part1[MROWS * FEATW];
__device__ float g_feat [MROWS * FEATW];
__device__ float g_bprep[16 * 300 * 64];   // [ntile][k][64 dup floats]

// ---- packed f32x2 helpers (sm_100+) --------------------------------------
__device__ __forceinline__ ull f2_pack(float x, float y) {
    ull r; asm("mov.b64 %0, {%1,%2};" : "=l"(r) : "f"(x), "f"(y)); return r;
}
__device__ __forceinline__ float2 f2_unpack(ull v) {
    float2 r; asm("mov.b64 {%0,%1}, %2;" : "=f"(r.x), "=f"(r.y) : "l"(v)); return r;
}
#define FMA2(d,a,b,c) asm("fma.rn.f32x2 %0, %1, %2, %3;" : "=l"(d) : "l"(a), "l"(b), "l"(c))
#define ADD2(d,a,b)   asm("add.rn.f32x2 %0, %1, %2;"     : "=l"(d) : "l"(a), "l"(b))

__device__ __forceinline__ void cpasync4(unsigned dst, const void* src) {
    asm volatile("cp.async.ca.shared.global [%0], [%1], 4;" :: "r"(dst), "l"(src));
}
__device__ __forceinline__ void cpasync16(unsigned dst, const void* src) {
    asm volatile("cp.async.cg.shared.global [%0], [%1], 16;" :: "r"(dst), "l"(src));
}

// ---------------------------------------------------------------------------
// Kernel 0: duplicate weights into tile-linear layout
// Bprep[nt][k][2j+h] = Wseg[(nt&3)*32+j][k], nt 0..15 (4 per segment)
// ---------------------------------------------------------------------------
__global__ __launch_bounds__(256) void prep_kernel(
    const float* __restrict__ Wl,  const float* __restrict__ Wr,
    const float* __restrict__ Ws1, const float* __restrict__ We1)
{
    const int t = blockIdx.x * 256 + threadIdx.x;      // 307200 exact
    const int nt = t / (300 * 64);
    const int r  = t % (300 * 64);
    const int k  = r >> 6;
    const int j  = (r & 63) >> 1;
    const int seg = nt >> 2;
    const int col = (nt & 3) * 32 + j;
    const float* W = seg == 0 ? Wl : seg == 1 ? Wr : seg == 2 ? Ws1 : We1;
    g_bprep[t] = W[col * 300 + k];
}

// ---------------------------------------------------------------------------
// Kernel 1: fused gather + GEMM partials. [2048 x 150] @ [150 x 512] x2
// BM=256, BN=32, BK=15, 128 thr, grid (8 Mtiles, 16 Ntiles, 2 Khalves)=256.
// Per-thread 4 m-pairs x 8 n = 32 FFMA2/k vs 12 smem wavefronts (ratio .375).
// cp.async double-buffered staging (zero staging registers).
// ---------------------------------------------------------------------------
#define GBK 15
#define PADA 260
#define PADB 68

__global__ __launch_bounds__(128, 4) void gemm_kernel(
    const int* __restrict__ sent, const float* __restrict__ emb)
{
    __shared__ __align__(16) float As[2][GBK * PADA];  // [k][m 0..255]
    __shared__ __align__(16) float Bs[2][GBK * PADB];  // [k][64 dup]
    __shared__ int rowidx[256];

    const int m0 = blockIdx.x * 256;
    const int nt = blockIdx.y;
    const int z  = blockIdx.z;
    const int kz = z * KHALF;
    float* gout  = z ? g_part1 : g_part0;

    const int tid = threadIdx.x;
    rowidx[tid]       = sent[m0 + tid];
    rowidx[tid + 128] = sent[m0 + tid + 128];
    __syncthreads();

    const float* a0src = emb + (long)rowidx[2 * tid]     * DD + kz;
    const float* a1src = emb + (long)rowidx[2 * tid + 1] * DD + kz;
    const float* bsrc  = g_bprep + ((long)nt * 300 + kz) * 64;

    const unsigned sA = (unsigned)__cvta_generic_to_shared(&As[0][0]);
    const unsigned sB = (unsigned)__cvta_generic_to_shared(&Bs[0][0]);
    const unsigned bufA = GBK * PADA * 4;
    const unsigned bufB = GBK * PADB * 4;

    // stage tile t into buffer c
    #define STAGE(t, c) do {                                                  \
        const unsigned dA = sA + (c) * bufA;                                  \
        _Pragma("unroll")                                                     \
        for (int k = 0; k < GBK; k++) {                                       \
            cpasync4(dA + (unsigned)(k * PADA + 2 * tid    ) * 4, a0src + (t) * GBK + k); \
            cpasync4(dA + (unsigned)(k * PADA + 2 * tid + 1) * 4, a1src + (t) * GBK + k); \
        }                                                                     \
        const unsigned dB = sB + (c) * bufB;                                  \
        cpasync16(dB + (unsigned)((tid >> 4) * PADB + (tid & 15) * 4) * 4,    \
                  bsrc + (t) * GBK * 64 + tid * 4);                           \
        if (tid < 112) {                                                      \
            const int f4 = tid + 128;                                         \
            cpasync16(dB + (unsigned)((f4 >> 4) * PADB + (f4 & 15) * 4) * 4,  \
                      bsrc + (t) * GBK * 64 + f4 * 4);                        \
        }                                                                     \
        asm volatile("cp.async.commit_group;" ::: "memory");                  \
    } while (0)

    const int lane = tid & 31;
    const int wid  = tid >> 5;        // warp -> 8 n columns [8w, 8w+8)

    ull acc[4][8];
    #pragma unroll
    for (int i = 0; i < 4; i++)
        #pragma unroll
        for (int n = 0; n < 8; n++) acc[i][n] = 0ull;

    STAGE(0, 0);

    for (int t = 0; t < 10; t++) {
        const int c = t & 1;
        if (t < 9) {
            STAGE(t + 1, c ^ 1);
            asm volatile("cp.async.wait_group 1;" ::: "memory");
        } else {
            asm volatile("cp.async.wait_group 0;" ::: "memory");
        }
        __syncthreads();

        #pragma unroll
        for (int k = 0; k < GBK; k++) {
            const float* ab = &As[c][k * PADA + 2 * lane];
            const ull a0 = *(const ull*)&ab[0];
            const ull a1 = *(const ull*)&ab[64];
            const ull a2 = *(const ull*)&ab[128];
            const ull a3 = *(const ull*)&ab[192];
            const ulonglong2* bp = (const ulonglong2*)&Bs[c][k * PADB + 16 * wid];
            const ulonglong2 b01 = bp[0], b23 = bp[1], b45 = bp[2], b67 = bp[3];
            const ull b[8] = {b01.x, b01.y, b23.x, b23.y, b45.x, b45.y, b67.x, b67.y};
            #pragma unroll
            for (int n = 0; n < 8; n++) {
                FMA2(acc[0][n], a0, b[n], acc[0][n]);
                FMA2(acc[1][n], a1, b[n], acc[1][n]);
                FMA2(acc[2][n], a2, b[n], acc[2][n]);
                FMA2(acc[3][n], a3, b[n], acc[3][n]);
            }
        }
        __syncthreads();   // buffer c may be overwritten by stage(t+2)
    }

    // epilogue: raw partial stores
    const int ng = nt * 32 + 8 * wid;          // global n base for this thread
    #pragma unroll
    for (int i = 0; i < 4; i++) {
        const int r0 = m0 + 2 * lane + 64 * i;
        float2 u[8];
        #pragma unroll
        for (int n = 0; n < 8; n++) u[n] = f2_unpack(acc[i][n]);
        float* o0 = &gout[(long)r0 * FEATW + ng];
        float* o1 = o0 + FEATW;
        *(float4*)&o0[0] = make_float4(u[0].x, u[1].x, u[2].x, u[3].x);
        *(float4*)&o0[4] = make_float4(u[4].x, u[5].x, u[6].x, u[7].x);
        *(float4*)&o1[0] = make_float4(u[0].y, u[1].y, u[2].y, u[3].y);
        *(float4*)&o1[4] = make_float4(u[4].y, u[5].y, u[6].y, u[7].y);
    }
    #undef STAGE
}

// ---------------------------------------------------------------------------
// Kernel 1b: combine partials once: g_feat = p0+p1 (+bias, relu on hs/he)
// ---------------------------------------------------------------------------
__global__ __launch_bounds__(256) void combine_kernel(
    const float* __restrict__ bl,
    const float* __restrict__ bs1, const float* __restrict__ be1)
{
    const int idx = blockIdx.x * 256 + threadIdx.x;    // float4 index, 262144
    const int col = (idx & 127) * 4;                   // 0..508
    const float4 a = *(const float4*)&g_part0[(long)idx * 4];
    const float4 b = *(const float4*)&g_part1[(long)idx * 4];
    float4 r = make_float4(a.x + b.x, a.y + b.y, a.z + b.z, a.w + b.w);
    if (col < 128) {                                   // left: + bl
        const float4 bb = *(const float4*)&bl[col];
        r.x += bb.x; r.y += bb.y; r.z += bb.z; r.w += bb.w;
    } else if (col >= 256) {                           // hs/he: + bias, relu
        const float4 bb = (col < 384) ? *(const float4*)&bs1[col - 256]
                                      : *(const float4*)&be1[col - 384];
        r.x = fmaxf(r.x + bb.x, 0.f); r.y = fmaxf(r.y + bb.y, 0.f);
        r.z = fmaxf(r.z + bb.z, 0.f); r.w = fmaxf(r.w + bb.w, 0.f);
    }                                                  // right: raw
    *(float4*)&g_feat[(long)idx * 4] = r;
}

// ---------------------------------------------------------------------------
// Kernel 2: start/end heads. One warp per row. (hs/he already relu'd)
// ---------------------------------------------------------------------------
__global__ __launch_bounds__(256) void startend_kernel(
    const float* __restrict__ Ws2, const float* __restrict__ bs2,
    const float* __restrict__ We2, const float* __restrict__ be2,
    float* __restrict__ out)
{
    const int warp = blockIdx.x * 8 + (threadIdx.x >> 5);
    const int lane = threadIdx.x & 31;
    const float* hs = &g_feat[warp * FEATW + 256];
    const float* he = &g_feat[warp * FEATW + 384];
    float s = 0.f, e = 0.f;
    #pragma unroll
    for (int u = 0; u < 4; u++) {
        const int p = lane + u * 32;
        s += hs[p] * Ws2[p];
        e += he[p] * We2[p];
    }
    #pragma unroll
    for (int o = 16; o; o >>= 1) {
        s += __shfl_xor_sync(0xFFFFFFFFu, s, o);
        e += __shfl_xor_sync(0xFFFFFFFFu, e, o);
    }
    if (lane == 0) {
        out[BB * NSEQ * NSEQ + warp]         = s + bs2[0];
        out[BB * NSEQ * NSEQ + MROWS + warp] = e + be2[0];
    }
}

// ---------------------------------------------------------------------------
// Kernel 3: bigram = relu(left[b,j,:] + right[b,i,:]) . Wo + bo   (R6 form)
// thread = one i (128 per block), 16 j per block; grid (16,2,8), 128 thr.
// ---------------------------------------------------------------------------
__global__ __launch_bounds__(128) void bigram_kernel(
    const float* __restrict__ Wo, const float* __restrict__ bo,
    float* __restrict__ out)
{
    __shared__ __align__(16) float Ls[2176];   // 16j x 128p; reused 128x17 transpose
    __shared__ __align__(16) float wos[128];

    const int b  = blockIdx.z;
    const int i0 = blockIdx.y * 128;
    const int j0 = blockIdx.x * 16;
    const int tid = threadIdx.x;

    for (int idx = tid; idx < 512; idx += 128) {
        const int r = idx >> 5, c4 = idx & 31;
        *(float4*)&Ls[r * 128 + c4 * 4] =
            *(const float4*)&g_feat[(long)(b * NSEQ + j0 + r) * FEATW + c4 * 4];
    }
    wos[tid] = Wo[tid];
    __syncthreads();

    const int i = i0 + tid;
    const float* rrow = &g_feat[(long)(b * NSEQ + i) * FEATW + 128];

    ull acc[16];
    #pragma unroll
    for (int j = 0; j < 16; j++) acc[j] = 0ull;

    float4 rc[4], rn[4];
    #pragma unroll
    for (int q = 0; q < 4; q++) rc[q] = *(const float4*)&rrow[q * 4];

    for (int pc = 0; pc < 8; pc++) {
        if (pc < 7) {
            #pragma unroll
            for (int q = 0; q < 4; q++) rn[q] = *(const float4*)&rrow[(pc + 1) * 16 + q * 4];
        }
        const ull* rv = (const ull*)rc;
        const ull* wv = (const ull*)&wos[pc * 16];
        const float* lbase = &Ls[pc * 16];

        #pragma unroll
        for (int up = 0; up < 4; up++) {
            const ull w0 = wv[2 * up], w1 = wv[2 * up + 1];
            const ull r0 = rv[2 * up], r1 = rv[2 * up + 1];
            #pragma unroll
            for (int j = 0; j < 16; j++) {
                const ull* lp = (const ull*)&lbase[j * 128 + 4 * up];
                ull s0; ADD2(s0, lp[0], r0);
                float2 f0 = f2_unpack(s0);
                f0.x = fmaxf(f0.x, 0.f); f0.y = fmaxf(f0.y, 0.f);
                FMA2(acc[j], f2_pack(f0.x, f0.y), w0, acc[j]);
                ull s1; ADD2(s1, lp[1], r1);
                float2 f1 = f2_unpack(s1);
                f1.x = fmaxf(f1.x, 0.f); f1.y = fmaxf(f1.y, 0.f);
                FMA2(acc[j], f2_pack(f1.x, f1.y), w1, acc[j]);
            }
        }
        #pragma unroll
        for (int q = 0; q < 4; q++) rc[q] = rn[q];
    }

    __syncthreads();
    const float bov = bo[0];
    #pragma unroll
    for (int j = 0; j < 16; j++) {
        const float2 a = f2_unpack(acc[j]);
        Ls[tid * 17 + j] = a.x + a.y + bov;
    }
    __syncthreads();
    #pragma unroll
    for (int it = 0; it < 4; it++) {
        const int f4 = it * 128 + tid;
        const int r  = f4 >> 2;
        const int jj = (f4 & 3) * 4;
        float4 v = make_float4(Ls[r * 17 + jj], Ls[r * 17 + jj + 1],
                               Ls[r * 17 + jj + 2], Ls[r * 17 + jj + 3]);
        *(float4*)&out[(long)(b * NSEQ + i0 + r) * NSEQ + j0 + jj] = v;
    }
}

// ---------------------------------------------------------------------------
extern "C" void kernel_launch(void* const* d_in, const int* in_sizes, int n_in,
                              void* d_out, int out_size)
{
    const int*   sent = (const int*)  d_in[0];
    const float* emb  = (const float*)d_in[1];
    const float* Wl   = (const float*)d_in[2];
    const float* bl   = (const float*)d_in[3];
    const float* Wr   = (const float*)d_in[4];
    const float* Wo   = (const float*)d_in[5];
    const float* bo   = (const float*)d_in[6];
    const float* Ws1  = (const float*)d_in[7];
    const float* bs1  = (const float*)d_in[8];
    const float* Ws2  = (const float*)d_in[9];
    const float* bs2  = (const float*)d_in[10];
    const float* We1  = (const float*)d_in[11];
    const float* be1  = (const float*)d_in[12];
    const float* We2  = (const float*)d_in[13];
    const float* be2  = (const float*)d_in[14];
    float* out = (float*)d_out;

    prep_kernel<<<1200, 256>>>(Wl, Wr, Ws1, We1);

    dim3 ggrid(8, 16, 2);
    gemm_kernel<<<ggrid, 128>>>(sent, emb);

    combine_kernel<<<1024, 256>>>(bl, bs1, be1);

    startend_kernel<<<256, 256>>>(Ws2, bs2, We2, be2, out);

    dim3 bgrid(16, 2, 8);
    bigram_kernel<<<bgrid, 128>>>(Wo, bo, out);
}

// round 10
// speedup vs baseline: 1.3212x; 1.3212x over previous
#include <cuda_runtime.h>

#define BB 8
#define NSEQ 256
#define DD 300
#define KHALF 150
#define MROWS (BB*NSEQ)          // 2048
#define FEATW 512                // left | right | hs | he
#define LRW 256                  // compact left|right width

typedef unsigned long long ull;

// K-half partials (raw), compact combined left|right features
__device__ float g_part0[MROWS * FEATW];
__device__ float g_part1[MROWS * FEATW];
__device__ float g_lr   [MROWS * LRW];   // [row][0:128 left+bl | 128:256 right]

// ---- packed f32x2 helpers (sm_100+) --------------------------------------
__device__ __forceinline__ ull f2_pack(float x, float y) {
    ull r; asm("mov.b64 %0, {%1,%2};" : "=l"(r) : "f"(x), "f"(y)); return r;
}
__device__ __forceinline__ float2 f2_unpack(ull v) {
    float2 r; asm("mov.b64 {%0,%1}, %2;" : "=f"(r.x), "=f"(r.y) : "l"(v)); return r;
}
#define FMA2(d,a,b,c) asm("fma.rn.f32x2 %0, %1, %2, %3;" : "=l"(d) : "l"(a), "l"(b), "l"(c))
#define ADD2(d,a,b)   asm("add.rn.f32x2 %0, %1, %2;"     : "=l"(d) : "l"(a), "l"(b))

// ---------------------------------------------------------------------------
// Kernel 1: fused gather + GEMM partials.  [2048 x 150] @ [150 x 512] x2
// grid (16 Mtiles, 8 Ntiles, 2 K-halves) = 256 blocks, 256 thr, 2 CTAs/SM.
// BM=128, BN=64, BK=30. f32x2 pairs over M; B duplicated (b,b) in smem,
// fetched as warp-uniform broadcast LDS.128. (R8 kernel, measured 28.4us)
// ---------------------------------------------------------------------------
__global__ __launch_bounds__(256, 2) void gemm_kernel(
    const int*   __restrict__ sent, const float* __restrict__ emb,
    const float* __restrict__ Wl,   const float* __restrict__ Wr,
    const float* __restrict__ Ws1,  const float* __restrict__ We1)
{
    const int BK = 30, PADA = 132, PADB = 132;
    __shared__ __align__(16) float As[2][BK * PADA];   // [k][m]      128 used
    __shared__ __align__(16) float Bs[2][BK * PADB];   // [k][2n dup] 128 used
    __shared__ int rowidx[128];

    const int m0  = blockIdx.x * 128;
    const int n0  = blockIdx.y * 64;
    const int z   = blockIdx.z;          // K half
    const int kz  = z * KHALF;
    const int seg = n0 >> 7;             // 0:left 1:right 2:hs 3:he
    const int nl0 = n0 & 127;

    const float* W;
    if      (seg == 0) W = Wl;
    else if (seg == 1) W = Wr;
    else if (seg == 2) W = Ws1;
    else               W = We1;
    float* gout = z ? g_part1 : g_part0;

    const int tid = threadIdx.x;
    if (tid < 128) rowidx[tid] = sent[m0 + tid];
    __syncthreads();

    // register prefetch: A tile 128x30 = 3840 = 15*256; B tile 64x30 = 1920
    float aR[15], bR[8];
    #pragma unroll
    for (int i = 0; i < 15; i++) {
        int idx = i * 256 + tid; int m = idx / 30; int k = idx - m * 30;
        aR[i] = emb[(long)rowidx[m] * DD + kz + k];
    }
    #pragma unroll
    for (int i = 0; i < 8; i++) {
        int idx = i * 256 + tid;
        if (idx < 1920) { int n = idx / 30; int k = idx - n * 30; bR[i] = W[(nl0 + n) * DD + kz + k]; }
    }

    const int lane = tid & 31;
    const int wid  = tid >> 5;           // warp -> 8 n-columns
    ull acc0[8], acc1[8];
    #pragma unroll
    for (int i = 0; i < 8; i++) { acc0[i] = 0ull; acc1[i] = 0ull; }

    for (int t = 0; t < 5; t++) {
        const int c = t & 1;
        #pragma unroll
        for (int i = 0; i < 15; i++) {
            int idx = i * 256 + tid; int m = idx / 30; int k = idx - m * 30;
            As[c][k * PADA + m] = aR[i];
        }
        #pragma unroll
        for (int i = 0; i < 8; i++) {
            int idx = i * 256 + tid;
            if (idx < 1920) { int n = idx / 30; int k = idx - n * 30;
                *(ull*)&Bs[c][k * PADB + 2 * n] = f2_pack(bR[i], bR[i]); }
        }
        __syncthreads();

        // prefetch next tile while computing on this one
        if (t < 4) {
            const int k0 = kz + (t + 1) * BK;
            #pragma unroll
            for (int i = 0; i < 15; i++) {
                int idx = i * 256 + tid; int m = idx / 30; int k = idx - m * 30;
                aR[i] = emb[(long)rowidx[m] * DD + k0 + k];
            }
            #pragma unroll
            for (int i = 0; i < 8; i++) {
                int idx = i * 256 + tid;
                if (idx < 1920) { int n = idx / 30; int k = idx - n * 30; bR[i] = W[(nl0 + n) * DD + k0 + k]; }
            }
        }

        #pragma unroll
        for (int k = 0; k < BK; k++) {
            const ull a0 = *(const ull*)&As[c][k * PADA + 2 * lane];       // (m, m+1)
            const ull a1 = *(const ull*)&As[c][k * PADA + 64 + 2 * lane];
            const ulonglong2* bp = (const ulonglong2*)&Bs[c][k * PADB + 16 * wid]; // bcast
            const ulonglong2 b01 = bp[0], b23 = bp[1], b45 = bp[2], b67 = bp[3];
            ull b[8] = {b01.x, b01.y, b23.x, b23.y, b45.x, b45.y, b67.x, b67.y};
            #pragma unroll
            for (int n = 0; n < 8; n++) {
                FMA2(acc0[n], a0, b[n], acc0[n]);
                FMA2(acc1[n], a1, b[n], acc1[n]);
            }
        }
        // next iter writes the other buffer; its __syncthreads guards reuse
    }

    // epilogue: raw partial store
    #pragma unroll
    for (int half = 0; half < 2; half++) {
        const ull* ac = half ? acc1 : acc0;
        const int mbase = m0 + half * 64 + 2 * lane;
        float2 u[8];
        #pragma unroll
        for (int n = 0; n < 8; n++) u[n] = f2_unpack(ac[n]);
        float* o0 = &gout[(long)mbase * FEATW + n0 + 8 * wid];
        float* o1 = o0 + FEATW;
        *(float4*)&o0[0] = make_float4(u[0].x, u[1].x, u[2].x, u[3].x);
        *(float4*)&o0[4] = make_float4(u[4].x, u[5].x, u[6].x, u[7].x);
        *(float4*)&o1[0] = make_float4(u[0].y, u[1].y, u[2].y, u[3].y);
        *(float4*)&o1[4] = make_float4(u[4].y, u[5].y, u[6].y, u[7].y);
    }
}

// ---------------------------------------------------------------------------
// Kernel 1b: combine left|right halves once: g_lr = p0+p1 (+bl on left).
// 2048 rows x 256 cols = 131072 float4 -> 512 blocks x 256 thr.
// ---------------------------------------------------------------------------
__global__ __launch_bounds__(256) void combine_kernel(const float* __restrict__ bl)
{
    const int idx = blockIdx.x * 256 + threadIdx.x;    // float4 index over g_lr
    const int row = idx >> 6;                          // 64 float4 per row
    const int c4  = idx & 63;
    const int col = c4 * 4;                            // 0..252
    const long src = (long)row * FEATW + col;
    const float4 a = *(const float4*)&g_part0[src];
    const float4 b = *(const float4*)&g_part1[src];
    float4 r = make_float4(a.x + b.x, a.y + b.y, a.z + b.z, a.w + b.w);
    if (col < 128) {                                   // left: + bl
        const float4 bb = *(const float4*)&bl[col];
        r.x += bb.x; r.y += bb.y; r.z += bb.z; r.w += bb.w;
    }
    *(float4*)&g_lr[(long)row * LRW + col] = r;
}

// ---------------------------------------------------------------------------
// Kernel 2: start/end heads from raw partials (fused sum+bias+relu+dot).
// ---------------------------------------------------------------------------
__global__ __launch_bounds__(256) void startend_kernel(
    const float* __restrict__ bs1, const float* __restrict__ be1,
    const float* __restrict__ Ws2, const float* __restrict__ bs2,
    const float* __restrict__ We2, const float* __restrict__ be2,
    float* __restrict__ out)
{
    const int warp = blockIdx.x * 8 + (threadIdx.x >> 5);
    const int lane = threadIdx.x & 31;
    const float* h0 = &g_part0[warp * FEATW + 256];
    const float* h1 = &g_part1[warp * FEATW + 256];
    float s = 0.f, e = 0.f;
    #pragma unroll
    for (int u = 0; u < 4; u++) {
        const int p = lane + u * 32;
        s += fmaxf(h0[p]       + h1[p]       + bs1[p], 0.f) * Ws2[p];
        e += fmaxf(h0[p + 128] + h1[p + 128] + be1[p], 0.f) * We2[p];
    }
    #pragma unroll
    for (int o = 16; o; o >>= 1) {
        s += __shfl_xor_sync(0xFFFFFFFFu, s, o);
        e += __shfl_xor_sync(0xFFFFFFFFu, e, o);
    }
    if (lane == 0) {
        out[BB * NSEQ * NSEQ + warp]         = s + bs2[0];
        out[BB * NSEQ * NSEQ + MROWS + warp] = e + be2[0];
    }
}

// ---------------------------------------------------------------------------
// Kernel 3: bigram = relu(left[b,j,:] + right[b,i,:]) . Wo + bo
// thread = one i (128 per block), 16 j per block; reads compact g_lr.
// right chunks in registers (double-buffered), left/Wo broadcast LDS.
// grid (16 jtiles, 2 itiles, 8 b), 128 threads.  (R6 form, stride 256)
// ---------------------------------------------------------------------------
__global__ __launch_bounds__(128) void bigram_kernel(
    const float* __restrict__ Wo, const float* __restrict__ bo,
    float* __restrict__ out)
{
    __shared__ __align__(16) float Ls[2176];   // 16j x 128p; reused 128x17 transpose
    __shared__ __align__(16) float wos[128];

    const int b  = blockIdx.z;
    const int i0 = blockIdx.y * 128;
    const int j0 = blockIdx.x * 16;
    const int tid = threadIdx.x;

    for (int idx = tid; idx < 512; idx += 128) {
        const int r = idx >> 5, c4 = idx & 31;
        *(float4*)&Ls[r * 128 + c4 * 4] =
            *(const float4*)&g_lr[(long)(b * NSEQ + j0 + r) * LRW + c4 * 4];
    }
    wos[tid] = Wo[tid];
    __syncthreads();

    const int i = i0 + tid;
    const float* rrow = &g_lr[(long)(b * NSEQ + i) * LRW + 128];

    ull acc[16];
    #pragma unroll
    for (int j = 0; j < 16; j++) acc[j] = 0ull;

    float4 rc[4], rn[4];
    #pragma unroll
    for (int q = 0; q < 4; q++) rc[q] = *(const float4*)&rrow[q * 4];

    for (int pc = 0; pc < 8; pc++) {
        if (pc < 7) {
            #pragma unroll
            for (int q = 0; q < 4; q++) rn[q] = *(const float4*)&rrow[(pc + 1) * 16 + q * 4];
        }
        const ull* rv = (const ull*)rc;
        const ull* wv = (const ull*)&wos[pc * 16];
        const float* lbase = &Ls[pc * 16];

        #pragma unroll
        for (int up = 0; up < 4; up++) {
            const ull w0 = wv[2 * up], w1 = wv[2 * up + 1];
            const ull r0 = rv[2 * up], r1 = rv[2 * up + 1];
            #pragma unroll
            for (int j = 0; j < 16; j++) {
                const ull* lp = (const ull*)&lbase[j * 128 + 4 * up];  // bcast LDS.128
                ull s0; ADD2(s0, lp[0], r0);
                float2 f0 = f2_unpack(s0);
                f0.x = fmaxf(f0.x, 0.f); f0.y = fmaxf(f0.y, 0.f);
                FMA2(acc[j], f2_pack(f0.x, f0.y), w0, acc[j]);
                ull s1; ADD2(s1, lp[1], r1);
                float2 f1 = f2_unpack(s1);
                f1.x = fmaxf(f1.x, 0.f); f1.y = fmaxf(f1.y, 0.f);
                FMA2(acc[j], f2_pack(f1.x, f1.y), w1, acc[j]);
            }
        }
        #pragma unroll
        for (int q = 0; q < 4; q++) rc[q] = rn[q];
    }

    // transpose through smem for coalesced output stores
    __syncthreads();
    const float bov = bo[0];
    #pragma unroll
    for (int j = 0; j < 16; j++) {
        const float2 a = f2_unpack(acc[j]);
        Ls[tid * 17 + j] = a.x + a.y + bov;
    }
    __syncthreads();
    #pragma unroll
    for (int it = 0; it < 4; it++) {
        const int f4 = it * 128 + tid;
        const int r  = f4 >> 2;
        const int jj = (f4 & 3) * 4;
        float4 v = make_float4(Ls[r * 17 + jj], Ls[r * 17 + jj + 1],
                               Ls[r * 17 + jj + 2], Ls[r * 17 + jj + 3]);
        *(float4*)&out[(long)(b * NSEQ + i0 + r) * NSEQ + j0 + jj] = v;
    }
}

// ---------------------------------------------------------------------------
extern "C" void kernel_launch(void* const* d_in, const int* in_sizes, int n_in,
                              void* d_out, int out_size)
{
    const int*   sent = (const int*)  d_in[0];
    const float* emb  = (const float*)d_in[1];
    const float* Wl   = (const float*)d_in[2];
    const float* bl   = (const float*)d_in[3];
    const float* Wr   = (const float*)d_in[4];
    const float* Wo   = (const float*)d_in[5];
    const float* bo   = (const float*)d_in[6];
    const float* Ws1  = (const float*)d_in[7];
    const float* bs1  = (const float*)d_in[8];
    const float* Ws2  = (const float*)d_in[9];
    const float* bs2  = (const float*)d_in[10];
    const float* We1  = (const float*)d_in[11];
    const float* be1  = (const float*)d_in[12];
    const float* We2  = (const float*)d_in[13];
    const float* be2  = (const float*)d_in[14];
    float* out = (float*)d_out;

    dim3 ggrid(16, 8, 2);
    gemm_kernel<<<ggrid, 256>>>(sent, emb, Wl, Wr, Ws1, We1);

    combine_kernel<<<512, 256>>>(bl);

    startend_kernel<<<256, 256>>>(bs1, be1, Ws2, bs2, We2, be2, out);

    dim3 bgrid(16, 2, 8);
    bigram_kernel<<<bgrid, 128>>>(Wo, bo, out);
}